// round 5
// baseline (speedup 1.0000x reference)
#include <cuda_runtime.h>

#define N_NODES 50000
#define N_EDGES 1600000

// Per-node precomputed readout vectors: [n][0..7] = c*A0[u], [n][8+u*3+k] = (c/sqrt3)*A1[u][k]
// One 128B line per node -> single-line gather in the edge kernel.
__device__ __align__(128) float g_prep[N_NODES * 32];

// SMEM layout (float offsets)
#define WF1_OFF 0        // 1*8*64  = 512   (layer1 B frags)
#define WF2_OFF 512      // 8*8*64  = 4096
#define WF3_OFF 4608     // 8*8*64  = 4096
#define WF4_OFF 8704     // 8*2*64  = 1024
#define H_OFF   9728     // 64*268  = 17152 (activations, edge-column-major)
#define H_STR   268      // stride mod 32 == 12 -> conflict-free A loads AND D stores
#define SMEM_FLOATS (H_OFF + 64 * H_STR)
#define SMEM_BYTES (SMEM_FLOATS * 4)   // 107,520 B -> 2 CTAs/SM

__device__ __forceinline__ float to_tf32(float x) {
    unsigned r;
    asm("cvt.rna.tf32.f32 %0, %1;" : "=r"(r) : "f"(x));
    return __uint_as_float(r);
}

// 4 silus with ONE rcp: 1/d_i reconstructed from group product (batched reciprocal).
__device__ __forceinline__ void silu4(float& x0, float& x1, float& x2, float& x3) {
    const float L2E = 1.4426950408889634f;
    float d0 = 1.f + exp2f(fminf(-x0, 15.f) * L2E);
    float d1 = 1.f + exp2f(fminf(-x1, 15.f) * L2E);
    float d2 = 1.f + exp2f(fminf(-x2, 15.f) * L2E);
    float d3 = 1.f + exp2f(fminf(-x3, 15.f) * L2E);
    float p01 = d0 * d1, p23 = d2 * d3;
    float rall;
    asm("rcp.approx.f32 %0, %1;" : "=f"(rall) : "f"(p01 * p23));
    float r01 = rall * p23, r23 = rall * p01;   // 1/(d0*d1), 1/(d2*d3)
    x0 = x0 * d1 * r01;
    x1 = x1 * d0 * r01;
    x2 = x2 * d3 * r23;
    x3 = x3 * d2 * r23;
}

__device__ __forceinline__ void mma_tf32(float* d, const unsigned* a, const unsigned* b) {
    asm volatile(
        "mma.sync.aligned.m16n8k8.row.col.f32.tf32.tf32.f32 "
        "{%0,%1,%2,%3}, {%4,%5,%6,%7}, {%8,%9}, {%0,%1,%2,%3};"
        : "+f"(d[0]), "+f"(d[1]), "+f"(d[2]), "+f"(d[3])
        : "r"(a[0]), "r"(a[1]), "r"(a[2]), "r"(a[3]), "r"(b[0]), "r"(b[1]));
}

__device__ __forceinline__ void red1(float* a, float v) {
    asm volatile("red.global.add.f32 [%0], %1;" :: "l"(a), "f"(v) : "memory");
}

// Fill fragment-ordered weights (tf32): dst[(kt*NT+nt)*64 + lane*2 + half]
__device__ __forceinline__ void fill_frags(float* dst, const float* __restrict__ w,
                                           int KT, int NT, int ncols, float scale, int tid) {
    const int total = KT * NT * 64;
    for (int idx = tid; idx < total; idx += 256) {
        int fi = idx >> 6, r = idx & 63;
        int lane = r >> 1, half = r & 1;
        int kt = fi / NT, nt = fi - kt * NT;
        int k = kt * 8 + (lane & 3) + half * 4;
        int n = nt * 8 + (lane >> 2);
        dst[idx] = to_tf32(w[k * ncols + n] * scale);
    }
}

template<int KT, int NT>
__device__ __forceinline__ void mma_layer(const float* __restrict__ wf,
                                          const float* __restrict__ h,
                                          int m0, int lane, float acc[][4]) {
    const int c = lane & 3, g = lane >> 2;
    #pragma unroll
    for (int kt = 0; kt < KT; kt++) {
        unsigned a[2][4];
        #pragma unroll
        for (int t = 0; t < 2; t++) {
            const float* base = h + (kt * 8 + c) * H_STR + m0 + 16 * t + g;
            a[t][0] = __float_as_uint(base[0]);
            a[t][1] = __float_as_uint(base[8]);
            a[t][2] = __float_as_uint(base[4 * H_STR]);
            a[t][3] = __float_as_uint(base[4 * H_STR + 8]);
        }
        #pragma unroll
        for (int nt = 0; nt < NT; nt++) {
            float2 bb = *(const float2*)(wf + (kt * NT + nt) * 64 + lane * 2);
            unsigned b[2] = { __float_as_uint(bb.x), __float_as_uint(bb.y) };
            mma_tf32(acc[0 * NT + nt], a[0], b);
            mma_tf32(acc[1 * NT + nt], a[1], b);
        }
    }
}

template<int NT, bool ACT>
__device__ __forceinline__ void store_acts(float* __restrict__ h, int m0, int lane,
                                           float acc[][4]) {
    const int c = lane & 3, g = lane >> 2;
    __syncwarp();   // all A reads of this warp complete before in-place writes
    #pragma unroll
    for (int t = 0; t < 2; t++) {
        #pragma unroll
        for (int nt = 0; nt < NT; nt++) {
            float* a4 = acc[t * NT + nt];
            float v0 = a4[0], v1 = a4[1], v2 = a4[2], v3 = a4[3];
            if (ACT) silu4(v0, v1, v2, v3);
            float* p = h + (nt * 8 + 2 * c) * H_STR + m0 + 16 * t + g;
            if (ACT) {
                p[0]         = to_tf32(v0);
                p[H_STR]     = to_tf32(v1);
                p[8]         = to_tf32(v2);
                p[H_STR + 8] = to_tf32(v3);
            } else {
                p[0] = v0; p[H_STR] = v1; p[8] = v2; p[H_STR + 8] = v3;
            }
        }
    }
    __syncwarp();
}

__global__ void __launch_bounds__(256, 2)
edge_kernel(const float* __restrict__ ef,   // edge_feats [E,8]
            const float* __restrict__ ea,   // edge_attrs [E,4]
            const float* __restrict__ qi,   // charges_induced [N,8]
            const int*   __restrict__ eidx, // edge_index [2,E]
            const float* __restrict__ w1,
            const float* __restrict__ w2,
            const float* __restrict__ w3,
            const float* __restrict__ w4,
            float* __restrict__ out)
{
    extern __shared__ float smem[];
    float* wf1 = smem + WF1_OFF;
    float* wf2 = smem + WF2_OFF;
    float* wf3 = smem + WF3_OFF;
    float* wf4 = smem + WF4_OFF;
    float* h   = smem + H_OFF;

    const int tid  = threadIdx.x;
    const int lane = tid & 31;
    const int m0   = (tid >> 5) * 32;
    const float s8  = 0.3535533905932738f;
    const float s64 = 0.125f;

    fill_frags(wf1, w1, 1, 8, 64, s8,  tid);
    fill_frags(wf2, w2, 8, 8, 64, s64, tid);
    fill_frags(wf3, w3, 8, 8, 64, s64, tid);
    fill_frags(wf4, w4, 8, 2, 16, s64, tid);

    const int e = blockIdx.x * 256 + tid;
    {
        float4 a4 = *(const float4*)(ef + (size_t)e * 8);
        float4 b4 = *(const float4*)(ef + (size_t)e * 8 + 4);
        h[0 * H_STR + tid] = to_tf32(a4.x);
        h[1 * H_STR + tid] = to_tf32(a4.y);
        h[2 * H_STR + tid] = to_tf32(a4.z);
        h[3 * H_STR + tid] = to_tf32(a4.w);
        h[4 * H_STR + tid] = to_tf32(b4.x);
        h[5 * H_STR + tid] = to_tf32(b4.y);
        h[6 * H_STR + tid] = to_tf32(b4.z);
        h[7 * H_STR + tid] = to_tf32(b4.w);
    }
    __syncthreads();

    float acc[16][4];

    #pragma unroll
    for (int i = 0; i < 16; i++) { acc[i][0]=0.f; acc[i][1]=0.f; acc[i][2]=0.f; acc[i][3]=0.f; }
    mma_layer<1, 8>(wf1, h, m0, lane, acc);
    store_acts<8, true>(h, m0, lane, acc);

    #pragma unroll
    for (int i = 0; i < 16; i++) { acc[i][0]=0.f; acc[i][1]=0.f; acc[i][2]=0.f; acc[i][3]=0.f; }
    mma_layer<8, 8>(wf2, h, m0, lane, acc);
    store_acts<8, true>(h, m0, lane, acc);

    #pragma unroll
    for (int i = 0; i < 16; i++) { acc[i][0]=0.f; acc[i][1]=0.f; acc[i][2]=0.f; acc[i][3]=0.f; }
    mma_layer<8, 8>(wf3, h, m0, lane, acc);
    store_acts<8, true>(h, m0, lane, acc);

    #pragma unroll
    for (int i = 0; i < 4; i++) { acc[i][0]=0.f; acc[i][1]=0.f; acc[i][2]=0.f; acc[i][3]=0.f; }
    mma_layer<8, 2>(wf4, h, m0, lane, acc);
    store_acts<2, false>(h, m0, lane, acc);

    float tp[16];
    #pragma unroll
    for (int j = 0; j < 16; j++) tp[j] = h[j * H_STR + tid];

    // ---- Gather sender charge + receiver readout row, contract to ONE scalar ----
    const int s = eidx[e];
    const int r = eidx[N_EDGES + e];
    float4 q0 = *(const float4*)(qi + (size_t)s * 8);
    float4 q1 = *(const float4*)(qi + (size_t)s * 8 + 4);
    float4 at = *(const float4*)(ea + (size_t)e * 4);
    float q[8] = {q0.x, q0.y, q0.z, q0.w, q1.x, q1.y, q1.z, q1.w};

    const float* pr = g_prep + (size_t)r * 32;   // one 128B line
    float A[32];
    #pragma unroll
    for (int i = 0; i < 8; i++) {
        float4 v = *(const float4*)(pr + i * 4);
        A[i*4+0] = v.x; A[i*4+1] = v.y; A[i*4+2] = v.z; A[i*4+3] = v.w;
    }

    float s0 = 0.f, s1 = 0.f;
    #pragma unroll
    for (int u = 0; u < 8; u++) {
        s0 = fmaf(tp[u] * q[u], A[u], s0);
        float bsum = at.y * A[8 + u*3 + 0];
        bsum = fmaf(at.z, A[8 + u*3 + 1], bsum);
        bsum = fmaf(at.w, A[8 + u*3 + 2], bsum);
        s1 = fmaf(tp[8 + u] * q[u], bsum, s1);
    }
    red1(out + r, fmaf(s0, at.x, s1));
}

// Warp per node: precompute per-node readout row into g_prep (consts folded).
__global__ void __launch_bounds__(256)
prep_kernel(const float* __restrict__ nf,   // node_feats [N,256]
            const float* __restrict__ W0,   // [8,64]
            const float* __restrict__ W1)   // [8,64]
{
    __shared__ float sW0[512], sW1[512];
    const int tid = threadIdx.x;
    for (int i = tid; i < 512; i += 256) { sW0[i] = W0[i]; sW1[i] = W1[i]; }
    __syncthreads();

    const int warp = tid >> 5;
    const int lane = tid & 31;
    const int n = blockIdx.x * 8 + warp;
    if (n >= N_NODES) return;

    const float* nrow = nf + (size_t)n * 256;
    const int v1 = lane, v2 = lane + 32;
    float x1 = nrow[v1], x2 = nrow[v2];
    float y1[3], y2[3];
    #pragma unroll
    for (int k = 0; k < 3; k++) {
        y1[k] = nrow[64 + v1 * 3 + k];
        y2[k] = nrow[64 + v2 * 3 + k];
    }

    float P[32];
    #pragma unroll
    for (int u = 0; u < 8; u++)
        P[u] = fmaf(sW0[u * 64 + v1], x1, sW0[u * 64 + v2] * x2);
    #pragma unroll
    for (int u = 0; u < 8; u++) {
        float wa = sW1[u * 64 + v1], wb = sW1[u * 64 + v2];
        #pragma unroll
        for (int k = 0; k < 3; k++)
            P[8 + u * 3 + k] = fmaf(wa, y1[k], wb * y2[k]);
    }

    #pragma unroll
    for (int off = 16; off; off >>= 1) {
        #pragma unroll
        for (int j = 0; j < 32; j++)
            P[j] += __shfl_xor_sync(0xffffffffu, P[j], off);
    }

    if (lane == 0) {
        const float c0 = 0.03125f;                 // 1/sqrt(8*64*2)
        const float c1 = 0.03125f * 0.5773502691896258f;  // c/sqrt(3)
        float* dst = g_prep + (size_t)n * 32;
        #pragma unroll
        for (int j = 0; j < 8; j++)  dst[j] = P[j] * c0;
        #pragma unroll
        for (int j = 8; j < 32; j++) dst[j] = P[j] * c1;
    }
}

extern "C" void kernel_launch(void* const* d_in, const int* in_sizes, int n_in,
                              void* d_out, int out_size)
{
    const float* node_feats      = (const float*)d_in[0];
    const float* charges_induced = (const float*)d_in[2];
    const float* edge_feats      = (const float*)d_in[3];
    const float* edge_attrs      = (const float*)d_in[4];
    const float* mlp_w1          = (const float*)d_in[6];
    const float* mlp_w2          = (const float*)d_in[7];
    const float* mlp_w3          = (const float*)d_in[8];
    const float* mlp_w4          = (const float*)d_in[9];
    const float* W0              = (const float*)d_in[10];
    const float* W1              = (const float*)d_in[11];
    const int*   eidx            = (const int*)d_in[12];
    float* out = (float*)d_out;

    cudaMemsetAsync(out, 0, (size_t)N_NODES * sizeof(float));

    prep_kernel<<<(N_NODES + 7) / 8, 256>>>(node_feats, W0, W1);

    cudaFuncSetAttribute(edge_kernel, cudaFuncAttributeMaxDynamicSharedMemorySize, SMEM_BYTES);
    edge_kernel<<<N_EDGES / 256, 256, SMEM_BYTES>>>(
        edge_feats, edge_attrs, charges_induced, eidx,
        mlp_w1, mlp_w2, mlp_w3, mlp_w4, out);
}

// round 7
// speedup vs baseline: 1.3222x; 1.3222x over previous
#include <cuda_runtime.h>

#define N_NODES 50000
#define N_EDGES 1600000

// Per-node precomputed readout vectors (one 128B line per node).
__device__ __align__(128) float g_prep[N_NODES * 32];
// Fragment-ordered tf32 weights, precomputed once.
__device__ __align__(16) float g_wfrags[9728];

// SMEM layout (float offsets)
#define WF1_OFF 0        // 1*8*64  = 512
#define WF2_OFF 512      // 8*8*64  = 4096
#define WF3_OFF 4608     // 8*8*64  = 4096
#define WF4_OFF 8704     // 8*2*64  = 1024
#define H_OFF   9728     // 64*268  = 17152
#define H_STR   268      // stride mod 32 == 12 -> conflict-free A loads AND D stores
#define SMEM_FLOATS (H_OFF + 64 * H_STR)
#define SMEM_BYTES (SMEM_FLOATS * 4)   // 107,520 B -> 2 CTAs/SM

#define NFRAG4 2432      // number of float4s in g_wfrags

__device__ __forceinline__ float to_tf32(float x) {
    unsigned r;
    asm("cvt.rna.tf32.f32 %0, %1;" : "=r"(r) : "f"(x));
    return __uint_as_float(r);
}

// 4 silus with ONE rcp (batched reciprocal).
__device__ __forceinline__ void silu4(float& x0, float& x1, float& x2, float& x3) {
    const float L2E = 1.4426950408889634f;
    float d0 = 1.f + exp2f(fminf(-x0, 15.f) * L2E);
    float d1 = 1.f + exp2f(fminf(-x1, 15.f) * L2E);
    float d2 = 1.f + exp2f(fminf(-x2, 15.f) * L2E);
    float d3 = 1.f + exp2f(fminf(-x3, 15.f) * L2E);
    float p01 = d0 * d1, p23 = d2 * d3;
    float rall;
    asm("rcp.approx.f32 %0, %1;" : "=f"(rall) : "f"(p01 * p23));
    float r01 = rall * p23, r23 = rall * p01;
    x0 = x0 * d1 * r01;
    x1 = x1 * d0 * r01;
    x2 = x2 * d3 * r23;
    x3 = x3 * d2 * r23;
}

__device__ __forceinline__ void mma_tf32(float* d, const unsigned* a, const unsigned* b) {
    asm volatile(
        "mma.sync.aligned.m16n8k8.row.col.f32.tf32.tf32.f32 "
        "{%0,%1,%2,%3}, {%4,%5,%6,%7}, {%8,%9}, {%0,%1,%2,%3};"
        : "+f"(d[0]), "+f"(d[1]), "+f"(d[2]), "+f"(d[3])
        : "r"(a[0]), "r"(a[1]), "r"(a[2]), "r"(a[3]), "r"(b[0]), "r"(b[1]));
}

__device__ __forceinline__ void red1(float* a, float v) {
    asm volatile("red.global.add.f32 [%0], %1;" :: "l"(a), "f"(v) : "memory");
}

// One-time: fragment-ordered tf32 weights -> g_wfrags (divisions OK here).
__device__ __forceinline__ void fill_frags_g(float* dst, const float* __restrict__ w,
                                             int KT, int NT, int ncols, float scale, int tid) {
    const int total = KT * NT * 64;
    for (int idx = tid; idx < total; idx += 256) {
        int fi = idx >> 6, r = idx & 63;
        int lane = r >> 1, half = r & 1;
        int kt = fi / NT, nt = fi - kt * NT;
        int k = kt * 8 + (lane & 3) + half * 4;
        int n = nt * 8 + (lane >> 2);
        dst[idx] = to_tf32(w[k * ncols + n] * scale);
    }
}

__global__ void __launch_bounds__(256)
frag_prep(const float* __restrict__ w1, const float* __restrict__ w2,
          const float* __restrict__ w3, const float* __restrict__ w4)
{
    const int tid = threadIdx.x;
    const float s8  = 0.3535533905932738f;
    const float s64 = 0.125f;
    fill_frags_g(g_wfrags + WF1_OFF, w1, 1, 8, 64, s8,  tid);
    fill_frags_g(g_wfrags + WF2_OFF, w2, 8, 8, 64, s64, tid);
    fill_frags_g(g_wfrags + WF3_OFF, w3, 8, 8, 64, s64, tid);
    fill_frags_g(g_wfrags + WF4_OFF, w4, 8, 2, 16, s64, tid);
}

template<int KT, int NT>
__device__ __forceinline__ void mma_layer(const float* __restrict__ wf,
                                          const float* __restrict__ h,
                                          int m0, int lane, float acc[][4]) {
    const int c = lane & 3, g = lane >> 2;
    #pragma unroll
    for (int kt = 0; kt < KT; kt++) {
        unsigned a[2][4];
        #pragma unroll
        for (int t = 0; t < 2; t++) {
            const float* base = h + (kt * 8 + c) * H_STR + m0 + 16 * t + g;
            a[t][0] = __float_as_uint(base[0]);
            a[t][1] = __float_as_uint(base[8]);
            a[t][2] = __float_as_uint(base[4 * H_STR]);
            a[t][3] = __float_as_uint(base[4 * H_STR + 8]);
        }
        #pragma unroll
        for (int nt = 0; nt < NT; nt++) {
            float2 bb = *(const float2*)(wf + (kt * NT + nt) * 64 + lane * 2);
            unsigned b[2] = { __float_as_uint(bb.x), __float_as_uint(bb.y) };
            mma_tf32(acc[0 * NT + nt], a[0], b);
            mma_tf32(acc[1 * NT + nt], a[1], b);
        }
    }
}

template<int NT, bool ACT>
__device__ __forceinline__ void store_acts(float* __restrict__ h, int m0, int lane,
                                           float acc[][4]) {
    const int c = lane & 3, g = lane >> 2;
    __syncwarp();
    #pragma unroll
    for (int t = 0; t < 2; t++) {
        #pragma unroll
        for (int nt = 0; nt < NT; nt++) {
            float* a4 = acc[t * NT + nt];
            float v0 = a4[0], v1 = a4[1], v2 = a4[2], v3 = a4[3];
            if (ACT) silu4(v0, v1, v2, v3);
            float* p = h + (nt * 8 + 2 * c) * H_STR + m0 + 16 * t + g;
            if (ACT) {
                p[0]         = to_tf32(v0);
                p[H_STR]     = to_tf32(v1);
                p[8]         = to_tf32(v2);
                p[H_STR + 8] = to_tf32(v3);
            } else {
                p[0] = v0; p[H_STR] = v1; p[8] = v2; p[H_STR + 8] = v3;
            }
        }
    }
    __syncwarp();
}

__global__ void __launch_bounds__(256, 2)
edge_kernel(const float* __restrict__ ef,   // edge_feats [E,8]
            const float* __restrict__ ea,   // edge_attrs [E,4]
            const float* __restrict__ qi,   // charges_induced [N,8]
            const int*   __restrict__ eidx, // edge_index [2,E]
            float* __restrict__ out)
{
    extern __shared__ float smem[];
    float* h = smem + H_OFF;

    const int tid  = threadIdx.x;
    const int lane = tid & 31;
    const int m0   = (tid >> 5) * 32;
    const int e    = blockIdx.x * 256 + tid;

    // ===== HEAD: issue all random-access loads first (latency hidden below) =====
    const int s = eidx[e];
    const int r = eidx[N_EDGES + e];
    float4 at = *(const float4*)(ea + (size_t)e * 4);
    float4 q0 = *(const float4*)(qi + (size_t)s * 8);
    float4 q1 = *(const float4*)(qi + (size_t)s * 8 + 4);
    const float* pr = g_prep + (size_t)r * 32;
    float4 Av[8];
    #pragma unroll
    for (int i = 0; i < 8; i++) Av[i] = *(const float4*)(pr + i * 4);

    // Copy precomputed weight frags to SMEM (coalesced, no arithmetic).
    // NFRAG4 = 2432 float4s -> ceil(2432/256) = 10 iterations. (R5 bug: only 9.)
    {
        const float4* src = (const float4*)g_wfrags;
        float4* dst = (float4*)smem;
        #pragma unroll
        for (int i = 0; i < 10; i++) {
            int idx = tid + i * 256;
            if (i < 9 || idx < NFRAG4) dst[idx] = src[idx];
        }
    }

    // Stage edge features (layer-1 A): h[f][col=tid], tf32-rounded.
    {
        float4 a4 = *(const float4*)(ef + (size_t)e * 8);
        float4 b4 = *(const float4*)(ef + (size_t)e * 8 + 4);
        h[0 * H_STR + tid] = to_tf32(a4.x);
        h[1 * H_STR + tid] = to_tf32(a4.y);
        h[2 * H_STR + tid] = to_tf32(a4.z);
        h[3 * H_STR + tid] = to_tf32(a4.w);
        h[4 * H_STR + tid] = to_tf32(b4.x);
        h[5 * H_STR + tid] = to_tf32(b4.y);
        h[6 * H_STR + tid] = to_tf32(b4.z);
        h[7 * H_STR + tid] = to_tf32(b4.w);
    }
    __syncthreads();

    // Contract gathered data into 16 registers (gather latency now amortized).
    float C0[8], C1[8];
    {
        float A[32];
        #pragma unroll
        for (int i = 0; i < 8; i++) {
            A[i*4+0] = Av[i].x; A[i*4+1] = Av[i].y;
            A[i*4+2] = Av[i].z; A[i*4+3] = Av[i].w;
        }
        float q[8] = {q0.x, q0.y, q0.z, q0.w, q1.x, q1.y, q1.z, q1.w};
        #pragma unroll
        for (int u = 0; u < 8; u++) {
            C0[u] = (q[u] * at.x) * A[u];
            float bsum = at.y * A[8 + u*3 + 0];
            bsum = fmaf(at.z, A[8 + u*3 + 1], bsum);
            bsum = fmaf(at.w, A[8 + u*3 + 2], bsum);
            C1[u] = q[u] * bsum;
        }
    }

    float acc[16][4];

    #pragma unroll
    for (int i = 0; i < 16; i++) { acc[i][0]=0.f; acc[i][1]=0.f; acc[i][2]=0.f; acc[i][3]=0.f; }
    mma_layer<1, 8>(smem + WF1_OFF, h, m0, lane, acc);
    store_acts<8, true>(h, m0, lane, acc);

    #pragma unroll
    for (int i = 0; i < 16; i++) { acc[i][0]=0.f; acc[i][1]=0.f; acc[i][2]=0.f; acc[i][3]=0.f; }
    mma_layer<8, 8>(smem + WF2_OFF, h, m0, lane, acc);
    store_acts<8, true>(h, m0, lane, acc);

    #pragma unroll
    for (int i = 0; i < 16; i++) { acc[i][0]=0.f; acc[i][1]=0.f; acc[i][2]=0.f; acc[i][3]=0.f; }
    mma_layer<8, 8>(smem + WF3_OFF, h, m0, lane, acc);
    store_acts<8, true>(h, m0, lane, acc);

    #pragma unroll
    for (int i = 0; i < 4; i++) { acc[i][0]=0.f; acc[i][1]=0.f; acc[i][2]=0.f; acc[i][3]=0.f; }
    mma_layer<8, 2>(smem + WF4_OFF, h, m0, lane, acc);
    store_acts<2, false>(h, m0, lane, acc);

    // Final: tp dot C -> one scalar atomic.
    float sres = 0.f;
    #pragma unroll
    for (int u = 0; u < 8; u++) {
        sres = fmaf(h[u * H_STR + tid], C0[u], sres);
        sres = fmaf(h[(8 + u) * H_STR + tid], C1[u], sres);
    }
    red1(out + r, sres);
}

// Warp per node: precompute per-node readout row into g_prep (consts folded).
__global__ void __launch_bounds__(256)
prep_kernel(const float* __restrict__ nf,   // node_feats [N,256]
            const float* __restrict__ W0,   // [8,64]
            const float* __restrict__ W1)   // [8,64]
{
    __shared__ float sW0[512], sW1[512];
    const int tid = threadIdx.x;
    for (int i = tid; i < 512; i += 256) { sW0[i] = W0[i]; sW1[i] = W1[i]; }
    __syncthreads();

    const int warp = tid >> 5;
    const int lane = tid & 31;
    const int n = blockIdx.x * 8 + warp;
    if (n >= N_NODES) return;

    const float* nrow = nf + (size_t)n * 256;
    const int v1 = lane, v2 = lane + 32;
    float x1 = nrow[v1], x2 = nrow[v2];
    float y1[3], y2[3];
    #pragma unroll
    for (int k = 0; k < 3; k++) {
        y1[k] = nrow[64 + v1 * 3 + k];
        y2[k] = nrow[64 + v2 * 3 + k];
    }

    float P[32];
    #pragma unroll
    for (int u = 0; u < 8; u++)
        P[u] = fmaf(sW0[u * 64 + v1], x1, sW0[u * 64 + v2] * x2);
    #pragma unroll
    for (int u = 0; u < 8; u++) {
        float wa = sW1[u * 64 + v1], wb = sW1[u * 64 + v2];
        #pragma unroll
        for (int k = 0; k < 3; k++)
            P[8 + u * 3 + k] = fmaf(wa, y1[k], wb * y2[k]);
    }

    #pragma unroll
    for (int off = 16; off; off >>= 1) {
        #pragma unroll
        for (int j = 0; j < 32; j++)
            P[j] += __shfl_xor_sync(0xffffffffu, P[j], off);
    }

    if (lane == 0) {
        const float c0 = 0.03125f;
        const float c1 = 0.03125f * 0.5773502691896258f;
        float* dst = g_prep + (size_t)n * 32;
        #pragma unroll
        for (int j = 0; j < 8; j++)  dst[j] = P[j] * c0;
        #pragma unroll
        for (int j = 8; j < 32; j++) dst[j] = P[j] * c1;
    }
}

extern "C" void kernel_launch(void* const* d_in, const int* in_sizes, int n_in,
                              void* d_out, int out_size)
{
    const float* node_feats      = (const float*)d_in[0];
    const float* charges_induced = (const float*)d_in[2];
    const float* edge_feats      = (const float*)d_in[3];
    const float* edge_attrs      = (const float*)d_in[4];
    const float* mlp_w1          = (const float*)d_in[6];
    const float* mlp_w2          = (const float*)d_in[7];
    const float* mlp_w3          = (const float*)d_in[8];
    const float* mlp_w4          = (const float*)d_in[9];
    const float* W0              = (const float*)d_in[10];
    const float* W1              = (const float*)d_in[11];
    const int*   eidx            = (const int*)d_in[12];
    float* out = (float*)d_out;

    cudaMemsetAsync(out, 0, (size_t)N_NODES * sizeof(float));

    frag_prep<<<1, 256>>>(mlp_w1, mlp_w2, mlp_w3, mlp_w4);
    prep_kernel<<<(N_NODES + 7) / 8, 256>>>(node_feats, W0, W1);

    cudaFuncSetAttribute(edge_kernel, cudaFuncAttributeMaxDynamicSharedMemorySize, SMEM_BYTES);
    edge_kernel<<<N_EDGES / 256, 256, SMEM_BYTES>>>(
        edge_feats, edge_attrs, charges_induced, eidx, out);
}

// round 8
// speedup vs baseline: 2.1551x; 1.6300x over previous
#include <cuda_runtime.h>
#include <cuda_fp16.h>

#define N_NODES 50000
#define N_EDGES 1600000

// Per-node precomputed readout vectors (one 128B line per node).
__device__ __align__(128) float g_prep[N_NODES * 32];
// Fragment-ordered fp16 weights (80 frags x 32 lanes x uint2), precomputed once.
__device__ uint2 g_wfrags2[2560];

// ---- SMEM layout (4-byte word offsets) ----
#define H2S      136        // half2-row stride; 136 mod 32 == 8 -> conflict-free
#define WF_WORDS 5120       // 2560 uint2
#define HP_OFF   5120       // 32 pair-rows x 136 words (half2) = 4352 words
#define CS_OFF   9472       // 16 rows x 136 floats = 2176 words
#define SMEM_WORDS 11648
#define SMEM_BYTES (SMEM_WORDS * 4)   // 46592 B -> 4 CTAs/SM

// frag base indices (in frag units of 32 uint2)
#define FB_L1 0
#define FB_L2 8
#define FB_L3 40
#define FB_L4 72

// 4 silus with ONE rcp (batched reciprocal).
__device__ __forceinline__ void silu4(float& x0, float& x1, float& x2, float& x3) {
    const float L2E = 1.4426950408889634f;
    float d0 = 1.f + exp2f(fminf(-x0, 15.f) * L2E);
    float d1 = 1.f + exp2f(fminf(-x1, 15.f) * L2E);
    float d2 = 1.f + exp2f(fminf(-x2, 15.f) * L2E);
    float d3 = 1.f + exp2f(fminf(-x3, 15.f) * L2E);
    float p01 = d0 * d1, p23 = d2 * d3;
    float rall;
    asm("rcp.approx.f32 %0, %1;" : "=f"(rall) : "f"(p01 * p23));
    float r01 = rall * p23, r23 = rall * p01;
    x0 = x0 * d1 * r01;
    x1 = x1 * d0 * r01;
    x2 = x2 * d3 * r23;
    x3 = x3 * d2 * r23;
}

__device__ __forceinline__ void mma_f16(float* d, unsigned a0, unsigned a1,
                                        unsigned a2, unsigned a3,
                                        unsigned b0, unsigned b1) {
    asm volatile(
        "mma.sync.aligned.m16n8k16.row.col.f32.f16.f16.f32 "
        "{%0,%1,%2,%3}, {%4,%5,%6,%7}, {%8,%9}, {%0,%1,%2,%3};"
        : "+f"(d[0]), "+f"(d[1]), "+f"(d[2]), "+f"(d[3])
        : "r"(a0), "r"(a1), "r"(a2), "r"(a3), "r"(b0), "r"(b1));
}

__device__ __forceinline__ void red1(float* a, float v) {
    asm volatile("red.global.add.f32 [%0], %1;" :: "l"(a), "f"(v) : "memory");
}

// One-time: fragment-ordered fp16 weights (zero-padded K) -> g_wfrags2.
__global__ void __launch_bounds__(256)
frag_prep(const float* __restrict__ w1, const float* __restrict__ w2,
          const float* __restrict__ w3, const float* __restrict__ w4)
{
    int idx = blockIdx.x * 256 + threadIdx.x;
    if (idx >= 2560) return;
    int f = idx >> 5, lane = idx & 31;
    int c = lane & 3, g = lane >> 2;
    const float s8 = 0.3535533905932738f, s64 = 0.125f;
    const float* w; int K, ncols, NT, fl; float scale;
    if (f < 8)       { w = w1; K = 8;  ncols = 64; NT = 8; fl = f;      scale = s8;  }
    else if (f < 40) { w = w2; K = 64; ncols = 64; NT = 8; fl = f - 8;  scale = s64; }
    else if (f < 72) { w = w3; K = 64; ncols = 64; NT = 8; fl = f - 40; scale = s64; }
    else             { w = w4; K = 64; ncols = 16; NT = 2; fl = f - 72; scale = s64; }
    int kt = fl / NT, nt = fl - kt * NT;
    int n = nt * 8 + g, kb = kt * 16 + 2 * c;
    float v0 = (kb     < K) ? w[(kb    ) * ncols + n] * scale : 0.f;
    float v1 = (kb + 1 < K) ? w[(kb + 1) * ncols + n] * scale : 0.f;
    float v2 = (kb + 8 < K) ? w[(kb + 8) * ncols + n] * scale : 0.f;
    float v3 = (kb + 9 < K) ? w[(kb + 9) * ncols + n] * scale : 0.f;
    __half2 x = __floats2half2_rn(v0, v1);
    __half2 y = __floats2half2_rn(v2, v3);
    g_wfrags2[idx] = make_uint2(*(unsigned*)&x, *(unsigned*)&y);
}

// Warp computes 16 edges (m0..m0+15) x NT*8 outputs, K = KT*16.
template<int KT, int NT>
__device__ __forceinline__ void mma_layer(const uint2* __restrict__ wf,
                                          const unsigned* __restrict__ hp,
                                          int m0, int lane, float acc[][4]) {
    const int c = lane & 3, g = lane >> 2;
    #pragma unroll
    for (int kt = 0; kt < KT; kt++) {
        unsigned a0 = hp[(kt * 8 + c)     * H2S + m0 + g];
        unsigned a1 = hp[(kt * 8 + c)     * H2S + m0 + g + 8];
        unsigned a2 = hp[(kt * 8 + c + 4) * H2S + m0 + g];
        unsigned a3 = hp[(kt * 8 + c + 4) * H2S + m0 + g + 8];
        #pragma unroll
        for (int nt = 0; nt < NT; nt++) {
            uint2 b = wf[(kt * NT + nt) * 32 + lane];
            mma_f16(acc[nt], a0, a1, a2, a3, b.x, b.y);
        }
    }
}

// silu + pack to half2, store all 32 pair-rows (NT=8).
template<int NT>
__device__ __forceinline__ void store_acts_h(unsigned* hp, int m0, int lane,
                                             float acc[][4]) {
    const int c = lane & 3, g = lane >> 2;
    __syncwarp();   // reads of hp complete before in-place writes
    #pragma unroll
    for (int nt = 0; nt < NT; nt++) {
        float v0 = acc[nt][0], v1 = acc[nt][1], v2 = acc[nt][2], v3 = acc[nt][3];
        silu4(v0, v1, v2, v3);
        __half2 p0 = __floats2half2_rn(v0, v1);
        __half2 p1 = __floats2half2_rn(v2, v3);
        hp[(nt * 4 + c) * H2S + m0 + g]     = *(unsigned*)&p0;
        hp[(nt * 4 + c) * H2S + m0 + g + 8] = *(unsigned*)&p1;
    }
    __syncwarp();
}

// Layer-4 output: store tp as fp32 rows 0..15 (no activation).
__device__ __forceinline__ void store_tp(float* fv, int m0, int lane, float acc[][4]) {
    const int c = lane & 3, g = lane >> 2;
    __syncwarp();
    #pragma unroll
    for (int nt = 0; nt < 2; nt++) {
        fv[(nt * 8 + 2 * c)     * H2S + m0 + g]     = acc[nt][0];
        fv[(nt * 8 + 2 * c + 1) * H2S + m0 + g]     = acc[nt][1];
        fv[(nt * 8 + 2 * c)     * H2S + m0 + g + 8] = acc[nt][2];
        fv[(nt * 8 + 2 * c + 1) * H2S + m0 + g + 8] = acc[nt][3];
    }
}

__global__ void __launch_bounds__(256, 4)
edge_kernel(const float* __restrict__ ef,   // edge_feats [E,8]
            const float* __restrict__ ea,   // edge_attrs [E,4]
            const float* __restrict__ qi,   // charges_induced [N,8]
            const int*   __restrict__ eidx, // edge_index [2,E]
            float* __restrict__ out)
{
    extern __shared__ float smem[];
    uint2*    wf  = (uint2*)smem;
    unsigned* hp  = (unsigned*)(smem + HP_OFF);
    float*    fv  = smem + HP_OFF;          // fp32 view of activation buffer
    float*    csm = smem + CS_OFF;

    const int tid  = threadIdx.x;
    const int lane = tid & 31;
    const int m0   = (tid >> 5) * 16;       // warp's 16-edge stripe
    const int eb   = blockIdx.x * 128;
    const bool gth = tid < 128;

    // Early LDGs for the gather (latency hidden under copy/staging below).
    int s = 0, r = 0;
    float4 at = make_float4(0.f, 0.f, 0.f, 0.f);
    if (gth) {
        s  = eidx[eb + tid];
        r  = eidx[N_EDGES + eb + tid];
        at = *(const float4*)(ea + (size_t)(eb + tid) * 4);
    }

    // Weight frags -> SMEM: 1280 float4, coalesced, no arithmetic.
    {
        const float4* src = (const float4*)g_wfrags2;
        float4* dst = (float4*)smem;
        #pragma unroll
        for (int i = 0; i < 5; i++) dst[tid + i * 256] = src[tid + i * 256];
    }

    // Stage layer-1 inputs: pair-rows 0..3 = features, 4..7 = zeros (k padding).
    {
        int m = tid & 127, sel = tid >> 7;
        if (sel == 0) {
            const float* base = ef + (size_t)(eb + m) * 8;
            float4 a4 = *(const float4*)base;
            float4 b4 = *(const float4*)(base + 4);
            __half2 p0 = __floats2half2_rn(a4.x, a4.y);
            __half2 p1 = __floats2half2_rn(a4.z, a4.w);
            __half2 p2 = __floats2half2_rn(b4.x, b4.y);
            __half2 p3 = __floats2half2_rn(b4.z, b4.w);
            hp[0 * H2S + m] = *(unsigned*)&p0;
            hp[1 * H2S + m] = *(unsigned*)&p1;
            hp[2 * H2S + m] = *(unsigned*)&p2;
            hp[3 * H2S + m] = *(unsigned*)&p3;
        } else {
            hp[4 * H2S + m] = 0u; hp[5 * H2S + m] = 0u;
            hp[6 * H2S + m] = 0u; hp[7 * H2S + m] = 0u;
        }
    }

    // Gather sender charge + receiver prep row; contract into csm[16][edge].
    if (gth) {
        float4 q0 = *(const float4*)(qi + (size_t)s * 8);
        float4 q1 = *(const float4*)(qi + (size_t)s * 8 + 4);
        const float4* pr = (const float4*)(g_prep + (size_t)r * 32);
        float q[8] = {q0.x, q0.y, q0.z, q0.w, q1.x, q1.y, q1.z, q1.w};
        float4 Aa = pr[0], Ab = pr[1];
        float A0[8] = {Aa.x, Aa.y, Aa.z, Aa.w, Ab.x, Ab.y, Ab.z, Ab.w};
        #pragma unroll
        for (int u = 0; u < 8; u++) csm[u * H2S + tid] = (q[u] * at.x) * A0[u];
        float A1[24];
        #pragma unroll
        for (int i = 0; i < 6; i++) {
            float4 v = pr[2 + i];
            A1[4*i] = v.x; A1[4*i+1] = v.y; A1[4*i+2] = v.z; A1[4*i+3] = v.w;
        }
        #pragma unroll
        for (int u = 0; u < 8; u++) {
            float b = at.y * A1[3*u];
            b = fmaf(at.z, A1[3*u + 1], b);
            b = fmaf(at.w, A1[3*u + 2], b);
            csm[(8 + u) * H2S + tid] = q[u] * b;
        }
    }
    __syncthreads();

    float acc[8][4];
    #define ZACC8 { _Pragma("unroll") for (int i = 0; i < 8; i++) { \
        acc[i][0]=0.f; acc[i][1]=0.f; acc[i][2]=0.f; acc[i][3]=0.f; } }

    ZACC8; mma_layer<1, 8>(wf + FB_L1 * 32, hp, m0, lane, acc);
    store_acts_h<8>(hp, m0, lane, acc);

    ZACC8; mma_layer<4, 8>(wf + FB_L2 * 32, hp, m0, lane, acc);
    store_acts_h<8>(hp, m0, lane, acc);

    ZACC8; mma_layer<4, 8>(wf + FB_L3 * 32, hp, m0, lane, acc);
    store_acts_h<8>(hp, m0, lane, acc);

    ZACC8; mma_layer<4, 2>(wf + FB_L4 * 32, hp, m0, lane, acc);
    store_tp(fv, m0, lane, acc);
    __syncthreads();

    // Tail: dot(tp[16], C[16]) -> one scalar atomic per edge.
    if (gth) {
        float sres = 0.f;
        #pragma unroll
        for (int j = 0; j < 16; j++)
            sres = fmaf(fv[j * H2S + tid], csm[j * H2S + tid], sres);
        red1(out + r, sres);
    }
}

// Warp per node: precompute per-node readout row into g_prep (consts folded).
__global__ void __launch_bounds__(256)
prep_kernel(const float* __restrict__ nf,   // node_feats [N,256]
            const float* __restrict__ W0,   // [8,64]
            const float* __restrict__ W1)   // [8,64]
{
    __shared__ float sW0[512], sW1[512];
    const int tid = threadIdx.x;
    for (int i = tid; i < 512; i += 256) { sW0[i] = W0[i]; sW1[i] = W1[i]; }
    __syncthreads();

    const int warp = tid >> 5;
    const int lane = tid & 31;
    const int n = blockIdx.x * 8 + warp;
    if (n >= N_NODES) return;

    const float* nrow = nf + (size_t)n * 256;
    const int v1 = lane, v2 = lane + 32;
    float x1 = nrow[v1], x2 = nrow[v2];
    float y1[3], y2[3];
    #pragma unroll
    for (int k = 0; k < 3; k++) {
        y1[k] = nrow[64 + v1 * 3 + k];
        y2[k] = nrow[64 + v2 * 3 + k];
    }

    float P[32];
    #pragma unroll
    for (int u = 0; u < 8; u++)
        P[u] = fmaf(sW0[u * 64 + v1], x1, sW0[u * 64 + v2] * x2);
    #pragma unroll
    for (int u = 0; u < 8; u++) {
        float wa = sW1[u * 64 + v1], wb = sW1[u * 64 + v2];
        #pragma unroll
        for (int k = 0; k < 3; k++)
            P[8 + u * 3 + k] = fmaf(wa, y1[k], wb * y2[k]);
    }

    #pragma unroll
    for (int off = 16; off; off >>= 1) {
        #pragma unroll
        for (int j = 0; j < 32; j++)
            P[j] += __shfl_xor_sync(0xffffffffu, P[j], off);
    }

    if (lane == 0) {
        const float c0 = 0.03125f;                        // 1/sqrt(8*64*2)
        const float c1 = 0.03125f * 0.5773502691896258f;  // c/sqrt(3)
        float* dst = g_prep + (size_t)n * 32;
        #pragma unroll
        for (int j = 0; j < 8; j++)  dst[j] = P[j] * c0;
        #pragma unroll
        for (int j = 8; j < 32; j++) dst[j] = P[j] * c1;
    }
}

extern "C" void kernel_launch(void* const* d_in, const int* in_sizes, int n_in,
                              void* d_out, int out_size)
{
    const float* node_feats      = (const float*)d_in[0];
    const float* charges_induced = (const float*)d_in[2];
    const float* edge_feats      = (const float*)d_in[3];
    const float* edge_attrs      = (const float*)d_in[4];
    const float* mlp_w1          = (const float*)d_in[6];
    const float* mlp_w2          = (const float*)d_in[7];
    const float* mlp_w3          = (const float*)d_in[8];
    const float* mlp_w4          = (const float*)d_in[9];
    const float* W0              = (const float*)d_in[10];
    const float* W1              = (const float*)d_in[11];
    const int*   eidx            = (const int*)d_in[12];
    float* out = (float*)d_out;

    cudaMemsetAsync(out, 0, (size_t)N_NODES * sizeof(float));

    frag_prep<<<10, 256>>>(mlp_w1, mlp_w2, mlp_w3, mlp_w4);
    prep_kernel<<<(N_NODES + 7) / 8, 256>>>(node_feats, W0, W1);

    cudaFuncSetAttribute(edge_kernel, cudaFuncAttributeMaxDynamicSharedMemorySize, SMEM_BYTES);
    edge_kernel<<<N_EDGES / 128, 256, SMEM_BYTES>>>(
        edge_feats, edge_attrs, charges_induced, eidx, out);
}

// round 9
// speedup vs baseline: 2.5384x; 1.1778x over previous
#include <cuda_runtime.h>
#include <cuda_fp16.h>

#define N_NODES 50000
#define N_EDGES 1600000
#define NB 4                 // 128-edge batches per CTA

// Per-node precomputed readout vectors (one 128B line per node).
__device__ __align__(128) float g_prep[N_NODES * 32];
// L1 k8 frags: 8 frags x 32 lanes (uint = half2)
__device__ __align__(16) unsigned g_wfrags1[256];
// L2/L3/L4 k16 frags: 72 frags x 32 lanes (uint2)
__device__ __align__(16) uint2 g_wfrags2[2304];

// ---- SMEM layout (4-byte word offsets) ----
#define H2S     136          // row stride; 136 mod 32 == 8 -> conflict-free
#define WF1_OFF 0            // 256 words
#define WF2_OFF 256          // 4608 words
#define HP_OFF  4864         // 32 pair-rows x 136
#define CS_OFF  9216         // 16 rows x 136
#define SMEM_WORDS 11392
#define SMEM_BYTES (SMEM_WORDS * 4)   // 45568 B -> 4 CTAs/SM

// frag bases inside wf2 (units of frags = 32 uint2)
#define FB_L2 0
#define FB_L3 32
#define FB_L4 64

__device__ __forceinline__ unsigned h2bits(__half2 h) { return *(unsigned*)&h; }

// silu via HW tanh, fully fp16x2: silu(x) = h + h*tanh(h), h = x/2.
__device__ __forceinline__ unsigned silu_h2(float x0, float x1) {
    __half2 h = __floats2half2_rn(x0, x1);
    __half2 hh = __hmul2(h, __floats2half2_rn(0.5f, 0.5f));
    unsigned t;
    asm("tanh.approx.f16x2 %0, %1;" : "=r"(t) : "r"(h2bits(hh)));
    __half2 r = __hfma2(hh, *(__half2*)&t, hh);
    return h2bits(r);
}

__device__ __forceinline__ void mma_f16(float* d, unsigned a0, unsigned a1,
                                        unsigned a2, unsigned a3,
                                        unsigned b0, unsigned b1) {
    asm volatile(
        "mma.sync.aligned.m16n8k16.row.col.f32.f16.f16.f32 "
        "{%0,%1,%2,%3}, {%4,%5,%6,%7}, {%8,%9}, {%0,%1,%2,%3};"
        : "+f"(d[0]), "+f"(d[1]), "+f"(d[2]), "+f"(d[3])
        : "r"(a0), "r"(a1), "r"(a2), "r"(a3), "r"(b0), "r"(b1));
}

__device__ __forceinline__ void mma_f16_k8(float* d, unsigned a0, unsigned a1, unsigned b0) {
    asm volatile(
        "mma.sync.aligned.m16n8k8.row.col.f32.f16.f16.f32 "
        "{%0,%1,%2,%3}, {%4,%5}, {%6}, {%0,%1,%2,%3};"
        : "+f"(d[0]), "+f"(d[1]), "+f"(d[2]), "+f"(d[3])
        : "r"(a0), "r"(a1), "r"(b0));
}

__device__ __forceinline__ void red1(float* a, float v) {
    asm volatile("red.global.add.f32 [%0], %1;" :: "l"(a), "f"(v) : "memory");
}

// One-time weight fragment pack (fp16, scale folded).
__global__ void __launch_bounds__(256)
frag_prep(const float* __restrict__ w1, const float* __restrict__ w2,
          const float* __restrict__ w3, const float* __restrict__ w4)
{
    int idx = blockIdx.x * 256 + threadIdx.x;
    const float s8 = 0.3535533905932738f, s64 = 0.125f;
    if (idx < 256) {
        // L1 k8 frag: frag f covers n = f*8..f*8+7; value = (w1[2c][n], w1[2c+1][n])
        int f = idx >> 5, lane = idx & 31;
        int c = lane & 3, g = lane >> 2;
        int n = f * 8 + g;
        __half2 p = __floats2half2_rn(w1[(2*c) * 64 + n] * s8,
                                      w1[(2*c + 1) * 64 + n] * s8);
        g_wfrags1[idx] = h2bits(p);
    } else if (idx < 2560) {
        int t = idx - 256;
        int f = t >> 5, lane = t & 31;
        int c = lane & 3, g = lane >> 2;
        const float* w; int ncols, NT, fl;
        if (f < 32)      { w = w2; ncols = 64; NT = 8; fl = f; }
        else if (f < 64) { w = w3; ncols = 64; NT = 8; fl = f - 32; }
        else             { w = w4; ncols = 16; NT = 2; fl = f - 64; }
        int kt = fl / NT, nt = fl - kt * NT;
        int n = nt * 8 + g, kb = kt * 16 + 2 * c;
        __half2 x = __floats2half2_rn(w[kb * ncols + n] * s64,
                                      w[(kb + 1) * ncols + n] * s64);
        __half2 y = __floats2half2_rn(w[(kb + 8) * ncols + n] * s64,
                                      w[(kb + 9) * ncols + n] * s64);
        g_wfrags2[t] = make_uint2(h2bits(x), h2bits(y));
    }
}

// k16 layer: warp computes 16 edges x NT*8 outputs over KT*16 K.
template<int KT, int NT>
__device__ __forceinline__ void mma_layer(const uint2* __restrict__ wf,
                                          const unsigned* __restrict__ hp,
                                          int m0, int lane, float acc[][4]) {
    const int c = lane & 3, g = lane >> 2;
    #pragma unroll
    for (int kt = 0; kt < KT; kt++) {
        unsigned a0 = hp[(kt * 8 + c)     * H2S + m0 + g];
        unsigned a1 = hp[(kt * 8 + c)     * H2S + m0 + g + 8];
        unsigned a2 = hp[(kt * 8 + c + 4) * H2S + m0 + g];
        unsigned a3 = hp[(kt * 8 + c + 4) * H2S + m0 + g + 8];
        #pragma unroll
        for (int nt = 0; nt < NT; nt++) {
            uint2 b = wf[(kt * NT + nt) * 32 + lane];
            mma_f16(acc[nt], a0, a1, a2, a3, b.x, b.y);
        }
    }
}

template<int NT>
__device__ __forceinline__ void store_acts_h(unsigned* hp, int m0, int lane,
                                             float acc[][4]) {
    const int c = lane & 3, g = lane >> 2;
    __syncwarp();   // reads of hp complete before in-place writes
    #pragma unroll
    for (int nt = 0; nt < NT; nt++) {
        hp[(nt * 4 + c) * H2S + m0 + g]     = silu_h2(acc[nt][0], acc[nt][1]);
        hp[(nt * 4 + c) * H2S + m0 + g + 8] = silu_h2(acc[nt][2], acc[nt][3]);
    }
    __syncwarp();
}

// Layer-4: store tp fp32 rows 0..15 (no activation).
__device__ __forceinline__ void store_tp(float* fv, int m0, int lane, float acc[][4]) {
    const int c = lane & 3, g = lane >> 2;
    __syncwarp();
    #pragma unroll
    for (int nt = 0; nt < 2; nt++) {
        fv[(nt * 8 + 2 * c)     * H2S + m0 + g]     = acc[nt][0];
        fv[(nt * 8 + 2 * c + 1) * H2S + m0 + g]     = acc[nt][1];
        fv[(nt * 8 + 2 * c)     * H2S + m0 + g + 8] = acc[nt][2];
        fv[(nt * 8 + 2 * c + 1) * H2S + m0 + g + 8] = acc[nt][3];
    }
    __syncwarp();
}

__global__ void __launch_bounds__(256, 4)
edge_kernel(const float* __restrict__ ef,   // edge_feats [E,8]
            const float* __restrict__ ea,   // edge_attrs [E,4]
            const float* __restrict__ qi,   // charges_induced [N,8]
            const int*   __restrict__ eidx, // edge_index [2,E]
            float* __restrict__ out)
{
    extern __shared__ float smem[];
    unsigned* wf1 = (unsigned*)smem;
    uint2*    wf2 = (uint2*)(smem + WF2_OFF);
    unsigned* hp  = (unsigned*)(smem + HP_OFF);
    float*    fv  = smem + HP_OFF;
    float*    csm = smem + CS_OFF;

    const int tid  = threadIdx.x;
    const int lane = tid & 31;
    const int m0   = (tid >> 5) * 16;
    const int half = lane & 1;
    const int cm   = m0 + (lane >> 1);   // this lane's edge column

    // Weight frags -> SMEM (block-cooperative; the only block sync).
    {
        const float4* s1 = (const float4*)g_wfrags1;   // 64 float4
        float4* d1 = (float4*)smem;
        if (tid < 64) d1[tid] = s1[tid];
        const float4* s2 = (const float4*)g_wfrags2;   // 1152 float4
        float4* d2 = (float4*)(smem + WF2_OFF);
        #pragma unroll
        for (int i = 0; i < 4; i++) d2[tid + i * 256] = s2[tid + i * 256];
        if (tid < 128) d2[tid + 1024] = s2[tid + 1024];
    }
    __syncthreads();

    float acc[8][4];
    #define ZACC(N) { _Pragma("unroll") for (int i = 0; i < N; i++) { \
        acc[i][0]=0.f; acc[i][1]=0.f; acc[i][2]=0.f; acc[i][3]=0.f; } }

    #pragma unroll 1
    for (int b = 0; b < NB; b++) {
        const int base = blockIdx.x * (128 * NB) + b * 128;
        const int me = base + cm;        // this lane's edge (2 lanes per edge)

        // ---- Gather + stage (warp-local) ----
        const int s_ = eidx[me];
        const int r_ = eidx[N_EDGES + me];
        float4 at = *(const float4*)(ea + (size_t)me * 4);
        float4 f4 = *(const float4*)(ef + (size_t)me * 8 + half * 4);
        float4 q0 = *(const float4*)(qi + (size_t)s_ * 8);
        float4 q1 = *(const float4*)(qi + (size_t)s_ * 8 + 4);
        const float4* pr = (const float4*)(g_prep + (size_t)r_ * 32);

        hp[(2 * half)     * H2S + cm] = h2bits(__floats2half2_rn(f4.x, f4.y));
        hp[(2 * half + 1) * H2S + cm] = h2bits(__floats2half2_rn(f4.z, f4.w));

        float q[8] = {q0.x, q0.y, q0.z, q0.w, q1.x, q1.y, q1.z, q1.w};
        if (half == 0) {
            float4 Aa = pr[0], Ab = pr[1];
            float A0[8] = {Aa.x, Aa.y, Aa.z, Aa.w, Ab.x, Ab.y, Ab.z, Ab.w};
            #pragma unroll
            for (int u = 0; u < 8; u++) csm[u * H2S + cm] = (q[u] * at.x) * A0[u];
        } else {
            float A1[24];
            #pragma unroll
            for (int i = 0; i < 6; i++) {
                float4 v = pr[2 + i];
                A1[4*i] = v.x; A1[4*i+1] = v.y; A1[4*i+2] = v.z; A1[4*i+3] = v.w;
            }
            #pragma unroll
            for (int u = 0; u < 8; u++) {
                float bs = at.y * A1[3*u];
                bs = fmaf(at.z, A1[3*u + 1], bs);
                bs = fmaf(at.w, A1[3*u + 2], bs);
                csm[(8 + u) * H2S + cm] = q[u] * bs;
            }
        }
        __syncwarp();

        // ---- Layer 1: 8 -> 64 (k8, no padding) ----
        ZACC(8);
        {
            const int c = lane & 3, g = lane >> 2;
            unsigned a0 = hp[c * H2S + m0 + g];
            unsigned a1 = hp[c * H2S + m0 + g + 8];
            #pragma unroll
            for (int nt = 0; nt < 8; nt++)
                mma_f16_k8(acc[nt], a0, a1, wf1[nt * 32 + lane]);
        }
        store_acts_h<8>(hp, m0, lane, acc);

        ZACC(8); mma_layer<4, 8>(wf2 + FB_L2 * 32, hp, m0, lane, acc);
        store_acts_h<8>(hp, m0, lane, acc);

        ZACC(8); mma_layer<4, 8>(wf2 + FB_L3 * 32, hp, m0, lane, acc);
        store_acts_h<8>(hp, m0, lane, acc);

        ZACC(2); mma_layer<4, 2>(wf2 + FB_L4 * 32, hp, m0, lane, acc);
        store_tp(fv, m0, lane, acc);

        // ---- Tail: dot(tp, C) -> one atomic per edge ----
        float sres = 0.f;
        #pragma unroll
        for (int j = 0; j < 8; j++) {
            int row = half * 8 + j;
            sres = fmaf(fv[row * H2S + cm], csm[row * H2S + cm], sres);
        }
        sres += __shfl_xor_sync(0xffffffffu, sres, 1);
        if (half == 0) red1(out + r_, sres);
        __syncwarp();   // tail reads done before next batch overwrites hp/csm
    }
}

// Warp per node: precompute per-node readout row into g_prep (consts folded).
__global__ void __launch_bounds__(256)
prep_kernel(const float* __restrict__ nf,   // node_feats [N,256]
            const float* __restrict__ W0,   // [8,64]
            const float* __restrict__ W1)   // [8,64]
{
    __shared__ float sW0[512], sW1[512];
    const int tid = threadIdx.x;
    for (int i = tid; i < 512; i += 256) { sW0[i] = W0[i]; sW1[i] = W1[i]; }
    __syncthreads();

    const int warp = tid >> 5;
    const int lane = tid & 31;
    const int n = blockIdx.x * 8 + warp;
    if (n >= N_NODES) return;

    const float* nrow = nf + (size_t)n * 256;
    const int v1 = lane, v2 = lane + 32;
    float x1 = nrow[v1], x2 = nrow[v2];
    float y1[3], y2[3];
    #pragma unroll
    for (int k = 0; k < 3; k++) {
        y1[k] = nrow[64 + v1 * 3 + k];
        y2[k] = nrow[64 + v2 * 3 + k];
    }

    float P[32];
    #pragma unroll
    for (int u = 0; u < 8; u++)
        P[u] = fmaf(sW0[u * 64 + v1], x1, sW0[u * 64 + v2] * x2);
    #pragma unroll
    for (int u = 0; u < 8; u++) {
        float wa = sW1[u * 64 + v1], wb = sW1[u * 64 + v2];
        #pragma unroll
        for (int k = 0; k < 3; k++)
            P[8 + u * 3 + k] = fmaf(wa, y1[k], wb * y2[k]);
    }

    #pragma unroll
    for (int off = 16; off; off >>= 1) {
        #pragma unroll
        for (int j = 0; j < 32; j++)
            P[j] += __shfl_xor_sync(0xffffffffu, P[j], off);
    }

    if (lane == 0) {
        const float c0 = 0.03125f;                        // 1/sqrt(8*64*2)
        const float c1 = 0.03125f * 0.5773502691896258f;  // c/sqrt(3)
        float* dst = g_prep + (size_t)n * 32;
        #pragma unroll
        for (int j = 0; j < 8; j++)  dst[j] = P[j] * c0;
        #pragma unroll
        for (int j = 8; j < 32; j++) dst[j] = P[j] * c1;
    }
}

extern "C" void kernel_launch(void* const* d_in, const int* in_sizes, int n_in,
                              void* d_out, int out_size)
{
    const float* node_feats      = (const float*)d_in[0];
    const float* charges_induced = (const float*)d_in[2];
    const float* edge_feats      = (const float*)d_in[3];
    const float* edge_attrs      = (const float*)d_in[4];
    const float* mlp_w1          = (const float*)d_in[6];
    const float* mlp_w2          = (const float*)d_in[7];
    const float* mlp_w3          = (const float*)d_in[8];
    const float* mlp_w4          = (const float*)d_in[9];
    const float* W0              = (const float*)d_in[10];
    const float* W1              = (const float*)d_in[11];
    const int*   eidx            = (const int*)d_in[12];
    float* out = (float*)d_out;

    cudaMemsetAsync(out, 0, (size_t)N_NODES * sizeof(float));

    frag_prep<<<10, 256>>>(mlp_w1, mlp_w2, mlp_w3, mlp_w4);
    prep_kernel<<<(N_NODES + 7) / 8, 256>>>(node_feats, W0, W1);

    cudaFuncSetAttribute(edge_kernel, cudaFuncAttributeMaxDynamicSharedMemorySize, SMEM_BYTES);
    edge_kernel<<<N_EDGES / (128 * NB), 256, SMEM_BYTES>>>(
        edge_feats, edge_attrs, charges_induced, eidx, out);
}

// round 10
// speedup vs baseline: 2.5790x; 1.0160x over previous
#include <cuda_runtime.h>
#include <cuda_fp16.h>

#define N_NODES 50000
#define N_EDGES 1600000
#define NB 5                 // 128-edge batches per CTA (grid = 1.6M/640 = 2500)

// Per-node precomputed readout vectors (one 128B line per node).
__device__ __align__(128) float g_prep[N_NODES * 32];
// L1 k8 frags: 8 frags x 32 lanes (uint = half2)
__device__ __align__(16) unsigned g_wfrags1[256];
// L2/L3/L4 k16 frags: 72 frags x 32 lanes (uint2)
__device__ __align__(16) uint2 g_wfrags2[2304];

// ---- SMEM layout (4-byte word offsets) ----
#define H2S     136          // row stride; 136 mod 32 == 8 -> conflict-free
#define WF1_OFF 0            // 256 words
#define WF2_OFF 256          // 4608 words
#define HP_OFF  4864         // 32 pair-rows x 136
#define CS_OFF  9216         // 16 rows x 136
#define SMEM_WORDS 11392
#define SMEM_BYTES (SMEM_WORDS * 4)   // 45568 B -> 4 CTAs/SM

// frag bases inside wf2 (units of frags = 32 uint2)
#define FB_L2 0
#define FB_L3 32
#define FB_L4 64

__device__ __forceinline__ unsigned h2bits(__half2 h) { return *(unsigned*)&h; }

// silu via HW tanh, fully fp16x2: silu(x) = h + h*tanh(h), h = x/2.
__device__ __forceinline__ unsigned silu_h2(float x0, float x1) {
    __half2 h = __floats2half2_rn(x0, x1);
    __half2 hh = __hmul2(h, __floats2half2_rn(0.5f, 0.5f));
    unsigned t;
    asm("tanh.approx.f16x2 %0, %1;" : "=r"(t) : "r"(h2bits(hh)));
    __half2 r = __hfma2(hh, *(__half2*)&t, hh);
    return h2bits(r);
}

__device__ __forceinline__ void mma_f16(float* d, unsigned a0, unsigned a1,
                                        unsigned a2, unsigned a3,
                                        unsigned b0, unsigned b1) {
    asm volatile(
        "mma.sync.aligned.m16n8k16.row.col.f32.f16.f16.f32 "
        "{%0,%1,%2,%3}, {%4,%5,%6,%7}, {%8,%9}, {%0,%1,%2,%3};"
        : "+f"(d[0]), "+f"(d[1]), "+f"(d[2]), "+f"(d[3])
        : "r"(a0), "r"(a1), "r"(a2), "r"(a3), "r"(b0), "r"(b1));
}

__device__ __forceinline__ void mma_f16_k8(float* d, unsigned a0, unsigned a1, unsigned b0) {
    asm volatile(
        "mma.sync.aligned.m16n8k8.row.col.f32.f16.f16.f32 "
        "{%0,%1,%2,%3}, {%4,%5}, {%6}, {%0,%1,%2,%3};"
        : "+f"(d[0]), "+f"(d[1]), "+f"(d[2]), "+f"(d[3])
        : "r"(a0), "r"(a1), "r"(b0));
}

__device__ __forceinline__ void red1(float* a, float v) {
    asm volatile("red.global.add.f32 [%0], %1;" :: "l"(a), "f"(v) : "memory");
}

// One-time weight fragment pack (fp16, scale folded).
__global__ void __launch_bounds__(256)
frag_prep(const float* __restrict__ w1, const float* __restrict__ w2,
          const float* __restrict__ w3, const float* __restrict__ w4)
{
    int idx = blockIdx.x * 256 + threadIdx.x;
    const float s8 = 0.3535533905932738f, s64 = 0.125f;
    if (idx < 256) {
        int f = idx >> 5, lane = idx & 31;
        int c = lane & 3, g = lane >> 2;
        int n = f * 8 + g;
        __half2 p = __floats2half2_rn(w1[(2*c) * 64 + n] * s8,
                                      w1[(2*c + 1) * 64 + n] * s8);
        g_wfrags1[idx] = h2bits(p);
    } else if (idx < 2560) {
        int t = idx - 256;
        int f = t >> 5, lane = t & 31;
        int c = lane & 3, g = lane >> 2;
        const float* w; int ncols, NT, fl;
        if (f < 32)      { w = w2; ncols = 64; NT = 8; fl = f; }
        else if (f < 64) { w = w3; ncols = 64; NT = 8; fl = f - 32; }
        else             { w = w4; ncols = 16; NT = 2; fl = f - 64; }
        int kt = fl / NT, nt = fl - kt * NT;
        int n = nt * 8 + g, kb = kt * 16 + 2 * c;
        __half2 x = __floats2half2_rn(w[kb * ncols + n] * s64,
                                      w[(kb + 1) * ncols + n] * s64);
        __half2 y = __floats2half2_rn(w[(kb + 8) * ncols + n] * s64,
                                      w[(kb + 9) * ncols + n] * s64);
        g_wfrags2[t] = make_uint2(h2bits(x), h2bits(y));
    }
}

// k16 layer: warp computes 16 edges x NT*8 outputs over KT*16 K.
template<int KT, int NT>
__device__ __forceinline__ void mma_layer(const uint2* __restrict__ wf,
                                          const unsigned* __restrict__ hp,
                                          int m0, int lane, float acc[][4]) {
    const int c = lane & 3, g = lane >> 2;
    #pragma unroll
    for (int kt = 0; kt < KT; kt++) {
        unsigned a0 = hp[(kt * 8 + c)     * H2S + m0 + g];
        unsigned a1 = hp[(kt * 8 + c)     * H2S + m0 + g + 8];
        unsigned a2 = hp[(kt * 8 + c + 4) * H2S + m0 + g];
        unsigned a3 = hp[(kt * 8 + c + 4) * H2S + m0 + g + 8];
        #pragma unroll
        for (int nt = 0; nt < NT; nt++) {
            uint2 b = wf[(kt * NT + nt) * 32 + lane];
            mma_f16(acc[nt], a0, a1, a2, a3, b.x, b.y);
        }
    }
}

template<int NT>
__device__ __forceinline__ void store_acts_h(unsigned* hp, int m0, int lane,
                                             float acc[][4]) {
    const int c = lane & 3, g = lane >> 2;
    __syncwarp();   // reads of hp complete before in-place writes
    #pragma unroll
    for (int nt = 0; nt < NT; nt++) {
        hp[(nt * 4 + c) * H2S + m0 + g]     = silu_h2(acc[nt][0], acc[nt][1]);
        hp[(nt * 4 + c) * H2S + m0 + g + 8] = silu_h2(acc[nt][2], acc[nt][3]);
    }
    __syncwarp();
}

__global__ void __launch_bounds__(256, 4)
edge_kernel(const float* __restrict__ ef,   // edge_feats [E,8]
            const float* __restrict__ ea,   // edge_attrs [E,4]
            const float* __restrict__ qi,   // charges_induced [N,8]
            const int*   __restrict__ eidx, // edge_index [2,E]
            float* __restrict__ out)
{
    extern __shared__ float smem[];
    unsigned* wf1 = (unsigned*)smem;
    uint2*    wf2 = (uint2*)(smem + WF2_OFF);
    unsigned* hp  = (unsigned*)(smem + HP_OFF);
    float*    csm = smem + CS_OFF;

    const int tid  = threadIdx.x;
    const int lane = tid & 31;
    const int m0   = (tid >> 5) * 16;
    const int half = lane & 1;
    const int cm   = m0 + (lane >> 1);   // this lane's edge column
    const int c    = lane & 3;
    const int g    = lane >> 2;

    // Weight frags -> SMEM (block-cooperative; the only block sync).
    {
        const float4* s1 = (const float4*)g_wfrags1;   // 64 float4
        float4* d1 = (float4*)smem;
        if (tid < 64) d1[tid] = s1[tid];
        const float4* s2 = (const float4*)g_wfrags2;   // 1152 float4
        float4* d2 = (float4*)(smem + WF2_OFF);
        #pragma unroll
        for (int i = 0; i < 4; i++) d2[tid + i * 256] = s2[tid + i * 256];
        if (tid < 128) d2[tid + 1024] = s2[tid + 1024];
    }
    __syncthreads();

    const int ebase = blockIdx.x * (128 * NB);

    // Prefetch batch 0's indices (breaks the eidx -> qi/prep chain).
    int s_n = eidx[ebase + cm];
    int r_n = eidx[N_EDGES + ebase + cm];

    float acc[8][4];
    #define ZACC(N) { _Pragma("unroll") for (int i = 0; i < N; i++) { \
        acc[i][0]=0.f; acc[i][1]=0.f; acc[i][2]=0.f; acc[i][3]=0.f; } }

    #pragma unroll 1
    for (int b = 0; b < NB; b++) {
        const int s_ = s_n;
        const int r_ = r_n;
        const int me = ebase + b * 128 + cm;

        // ---- Single parallel LDG round: at, f4, q, prep all issue together ----
        float4 at = *(const float4*)(ea + (size_t)me * 4);
        float4 f4 = *(const float4*)(ef + (size_t)me * 8 + half * 4);
        float4 q0 = *(const float4*)(qi + (size_t)s_ * 8);
        float4 q1 = *(const float4*)(qi + (size_t)s_ * 8 + 4);
        const float4* pr = (const float4*)(g_prep + (size_t)r_ * 32);

        // Prefetch next batch's indices (independent; overlaps everything).
        if (b + 1 < NB) {
            s_n = eidx[ebase + (b + 1) * 128 + cm];
            r_n = eidx[N_EDGES + ebase + (b + 1) * 128 + cm];
        }

        // Stage layer-1 inputs.
        hp[(2 * half)     * H2S + cm] = h2bits(__floats2half2_rn(f4.x, f4.y));
        hp[(2 * half + 1) * H2S + cm] = h2bits(__floats2half2_rn(f4.z, f4.w));

        // Contract gather into csm[16][edge].
        float q[8] = {q0.x, q0.y, q0.z, q0.w, q1.x, q1.y, q1.z, q1.w};
        if (half == 0) {
            float4 Aa = pr[0], Ab = pr[1];
            float A0[8] = {Aa.x, Aa.y, Aa.z, Aa.w, Ab.x, Ab.y, Ab.z, Ab.w};
            #pragma unroll
            for (int u = 0; u < 8; u++) csm[u * H2S + cm] = (q[u] * at.x) * A0[u];
        } else {
            float A1[24];
            #pragma unroll
            for (int i = 0; i < 6; i++) {
                float4 v = pr[2 + i];
                A1[4*i] = v.x; A1[4*i+1] = v.y; A1[4*i+2] = v.z; A1[4*i+3] = v.w;
            }
            #pragma unroll
            for (int u = 0; u < 8; u++) {
                float bs = at.y * A1[3*u];
                bs = fmaf(at.z, A1[3*u + 1], bs);
                bs = fmaf(at.w, A1[3*u + 2], bs);
                csm[(8 + u) * H2S + cm] = q[u] * bs;
            }
        }
        __syncwarp();

        // ---- Layer 1: 8 -> 64 (k8) ----
        ZACC(8);
        {
            unsigned a0 = hp[c * H2S + m0 + g];
            unsigned a1 = hp[c * H2S + m0 + g + 8];
            #pragma unroll
            for (int nt = 0; nt < 8; nt++)
                mma_f16_k8(acc[nt], a0, a1, wf1[nt * 32 + lane]);
        }
        store_acts_h<8>(hp, m0, lane, acc);

        ZACC(8); mma_layer<4, 8>(wf2 + FB_L2 * 32, hp, m0, lane, acc);
        store_acts_h<8>(hp, m0, lane, acc);

        ZACC(8); mma_layer<4, 8>(wf2 + FB_L3 * 32, hp, m0, lane, acc);
        store_acts_h<8>(hp, m0, lane, acc);

        // ---- Layer 4: 64 -> 16, tail directly in D-fragment domain ----
        ZACC(2); mma_layer<4, 2>(wf2 + FB_L4 * 32, hp, m0, lane, acc);

        // Thread (g,c) holds tp rows {g, g+8} x cols {nt*8+2c, nt*8+2c+1}.
        float sA = 0.f, sB = 0.f;
        #pragma unroll
        for (int nt = 0; nt < 2; nt++) {
            const float* cr0 = csm + (nt * 8 + 2 * c) * H2S + m0;
            const float* cr1 = cr0 + H2S;
            sA = fmaf(acc[nt][0], cr0[g],     sA);
            sA = fmaf(acc[nt][1], cr1[g],     sA);
            sB = fmaf(acc[nt][2], cr0[g + 8], sB);
            sB = fmaf(acc[nt][3], cr1[g + 8], sB);
        }
        sA += __shfl_xor_sync(0xffffffffu, sA, 1);
        sA += __shfl_xor_sync(0xffffffffu, sA, 2);
        sB += __shfl_xor_sync(0xffffffffu, sB, 1);
        sB += __shfl_xor_sync(0xffffffffu, sB, 2);
        // Receiver of edge m0+g lives in lane 2g; of edge m0+g+8 in lane 2g+16.
        int rg  = __shfl_sync(0xffffffffu, r_, 2 * g);
        int rg8 = __shfl_sync(0xffffffffu, r_, 2 * g + 16);
        if (c == 0) {
            red1(out + rg,  sA);
            red1(out + rg8, sB);
        }
        __syncwarp();   // tail csm/hp reads done before next batch overwrites
    }
}

// Warp per node: precompute per-node readout row into g_prep (consts folded).
__global__ void __launch_bounds__(256)
prep_kernel(const float* __restrict__ nf,   // node_feats [N,256]
            const float* __restrict__ W0,   // [8,64]
            const float* __restrict__ W1)   // [8,64]
{
    __shared__ float sW0[512], sW1[512];
    const int tid = threadIdx.x;
    for (int i = tid; i < 512; i += 256) { sW0[i] = W0[i]; sW1[i] = W1[i]; }
    __syncthreads();

    const int warp = tid >> 5;
    const int lane = tid & 31;
    const int n = blockIdx.x * 8 + warp;
    if (n >= N_NODES) return;

    const float* nrow = nf + (size_t)n * 256;
    const int v1 = lane, v2 = lane + 32;
    float x1 = nrow[v1], x2 = nrow[v2];
    float y1[3], y2[3];
    #pragma unroll
    for (int k = 0; k < 3; k++) {
        y1[k] = nrow[64 + v1 * 3 + k];
        y2[k] = nrow[64 + v2 * 3 + k];
    }

    float P[32];
    #pragma unroll
    for (int u = 0; u < 8; u++)
        P[u] = fmaf(sW0[u * 64 + v1], x1, sW0[u * 64 + v2] * x2);
    #pragma unroll
    for (int u = 0; u < 8; u++) {
        float wa = sW1[u * 64 + v1], wb = sW1[u * 64 + v2];
        #pragma unroll
        for (int k = 0; k < 3; k++)
            P[8 + u * 3 + k] = fmaf(wa, y1[k], wb * y2[k]);
    }

    #pragma unroll
    for (int off = 16; off; off >>= 1) {
        #pragma unroll
        for (int j = 0; j < 32; j++)
            P[j] += __shfl_xor_sync(0xffffffffu, P[j], off);
    }

    if (lane == 0) {
        const float c0 = 0.03125f;                        // 1/sqrt(8*64*2)
        const float c1 = 0.03125f * 0.5773502691896258f;  // c/sqrt(3)
        float* dst = g_prep + (size_t)n * 32;
        #pragma unroll
        for (int j = 0; j < 8; j++)  dst[j] = P[j] * c0;
        #pragma unroll
        for (int j = 8; j < 32; j++) dst[j] = P[j] * c1;
    }
}

extern "C" void kernel_launch(void* const* d_in, const int* in_sizes, int n_in,
                              void* d_out, int out_size)
{
    const float* node_feats      = (const float*)d_in[0];
    const float* charges_induced = (const float*)d_in[2];
    const float* edge_feats      = (const float*)d_in[3];
    const float* edge_attrs      = (const float*)d_in[4];
    const float* mlp_w1          = (const float*)d_in[6];
    const float* mlp_w2          = (const float*)d_in[7];
    const float* mlp_w3          = (const float*)d_in[8];
    const float* mlp_w4          = (const float*)d_in[9];
    const float* W0              = (const float*)d_in[10];
    const float* W1              = (const float*)d_in[11];
    const int*   eidx            = (const int*)d_in[12];
    float* out = (float*)d_out;

    cudaMemsetAsync(out, 0, (size_t)N_NODES * sizeof(float));

    frag_prep<<<10, 256>>>(mlp_w1, mlp_w2, mlp_w3, mlp_w4);
    prep_kernel<<<(N_NODES + 7) / 8, 256>>>(node_feats, W0, W1);

    cudaFuncSetAttribute(edge_kernel, cudaFuncAttributeMaxDynamicSharedMemorySize, SMEM_BYTES);
    edge_kernel<<<N_EDGES / (128 * NB), 256, SMEM_BYTES>>>(
        edge_feats, edge_attrs, charges_induced, eidx, out);
}